// round 1
// baseline (speedup 1.0000x reference)
#include <cuda_runtime.h>

#define DM   1024      // d_model
#define NE   8         // experts
#define FF   2048      // ffn dim
#define MAXT 4096      // max tokens
#define TM   64
#define TN   64
#define TK   16

// -------- persistent device scratch (no dynamic allocation allowed) --------
__device__ int   g_cnt[NE];
__device__ int   g_tok[NE * MAXT];
__device__ float g_wt [NE * MAXT];
__device__ float g_act[(size_t)NE * MAXT * FF];   // expert-local SwiGLU activations

// --------------------------------------------------------------------------
__global__ void init_k() {
    if (threadIdx.x < NE) g_cnt[threadIdx.x] = 0;
}

// one block per token: 8 warps compute 8 expert logits, thread 0 does top-2
__global__ void router_k(const float* __restrict__ x,
                         const float* __restrict__ Wr,
                         const float* __restrict__ temp) {
    __shared__ float xs[DM];
    __shared__ float lg[NE];
    int t = blockIdx.x;
    const float* xr = x + (size_t)t * DM;
    for (int i = threadIdx.x; i < DM; i += blockDim.x) xs[i] = xr[i];
    __syncthreads();
    int w = threadIdx.x >> 5, lane = threadIdx.x & 31;
    if (w < NE) {
        const float* wr = Wr + (size_t)w * DM;
        float s = 0.f;
        for (int i = lane; i < DM; i += 32) s += xs[i] * wr[i];
        #pragma unroll
        for (int o = 16; o; o >>= 1) s += __shfl_xor_sync(0xffffffffu, s, o);
        if (lane == 0) lg[w] = s;
    }
    __syncthreads();
    if (threadIdx.x == 0) {
        float it = 1.f / temp[0];
        float l[NE];
        #pragma unroll
        for (int e = 0; e < NE; e++) l[e] = lg[e] * it;
        int i0 = 0;
        #pragma unroll
        for (int e = 1; e < NE; e++) if (l[e] > l[i0]) i0 = e;     // first max
        int i1 = (i0 == 0) ? 1 : 0;
        #pragma unroll
        for (int e = 0; e < NE; e++)
            if (e != i0 && l[e] > l[i1]) i1 = e;                   // first 2nd max
        float m  = l[i0];
        float e0 = __expf(l[i0] - m), e1 = __expf(l[i1] - m);
        float inv = 1.f / (e0 + e1);
        int s0 = atomicAdd(&g_cnt[i0], 1);
        g_tok[i0 * MAXT + s0] = t;  g_wt[i0 * MAXT + s0] = e0 * inv;
        int s1 = atomicAdd(&g_cnt[i1], 1);
        g_tok[i1 * MAXT + s1] = t;  g_wt[i1 * MAXT + s1] = e1 * inv;
    }
}

// --------------------------------------------------------------------------
// GEMM1: a[m, n] = (x_g @ W1e[:F].T + b1a) * silu(x_g @ W1e[F:].T + b1b)
// 64x64 tile, TK=16, 4x4 per-thread microtile, dual B tiles.
__global__ __launch_bounds__(256) void gemm1_k(const float* __restrict__ x,
                                               const float* __restrict__ W1,
                                               const float* __restrict__ b1) {
    int e   = blockIdx.z;
    int cnt = g_cnt[e];
    int m0  = blockIdx.y * TM;
    if (m0 >= cnt) return;
    int n0  = blockIdx.x * TN;

    __shared__ float As[TK][TM];
    __shared__ float Bs[TK][TN];
    __shared__ float Cs[TK][TN];
    __shared__ int   toks[TM];

    int tid = threadIdx.x;
    if (tid < TM) {
        int m = m0 + tid;
        toks[tid] = (m < cnt) ? g_tok[e * MAXT + m] : -1;
    }
    __syncthreads();

    const float* W1e = W1 + (size_t)e * (2 * FF) * DM;
    int r  = tid >> 2, q = tid & 3;          // loader mapping: 64 rows x 4 quads
    int tx = tid & 15, ty = tid >> 4;        // compute mapping: 16x16 threads

    float acc1[4][4], acc2[4][4];
    #pragma unroll
    for (int i = 0; i < 4; i++)
        #pragma unroll
        for (int j = 0; j < 4; j++) { acc1[i][j] = 0.f; acc2[i][j] = 0.f; }

    int tok_r = toks[r];
    const float* arow = (tok_r >= 0) ? (x + (size_t)tok_r * DM) : nullptr;
    const float* brow = W1e + (size_t)(n0 + r) * DM;
    const float* crow = W1e + (size_t)(FF + n0 + r) * DM;

    for (int k0 = 0; k0 < DM; k0 += TK) {
        float4 va = arow ? *(const float4*)(arow + k0 + q * 4)
                         : make_float4(0.f, 0.f, 0.f, 0.f);
        float4 vb = *(const float4*)(brow + k0 + q * 4);
        float4 vc = *(const float4*)(crow + k0 + q * 4);
        As[q*4+0][r] = va.x; As[q*4+1][r] = va.y; As[q*4+2][r] = va.z; As[q*4+3][r] = va.w;
        Bs[q*4+0][r] = vb.x; Bs[q*4+1][r] = vb.y; Bs[q*4+2][r] = vb.z; Bs[q*4+3][r] = vb.w;
        Cs[q*4+0][r] = vc.x; Cs[q*4+1][r] = vc.y; Cs[q*4+2][r] = vc.z; Cs[q*4+3][r] = vc.w;
        __syncthreads();
        #pragma unroll
        for (int kk = 0; kk < TK; kk++) {
            float4 a4 = *(const float4*)&As[kk][ty * 4];
            float4 b4 = *(const float4*)&Bs[kk][tx * 4];
            float4 c4 = *(const float4*)&Cs[kk][tx * 4];
            float av[4] = {a4.x, a4.y, a4.z, a4.w};
            float bv[4] = {b4.x, b4.y, b4.z, b4.w};
            float cv[4] = {c4.x, c4.y, c4.z, c4.w};
            #pragma unroll
            for (int i = 0; i < 4; i++)
                #pragma unroll
                for (int j = 0; j < 4; j++) {
                    acc1[i][j] += av[i] * bv[j];
                    acc2[i][j] += av[i] * cv[j];
                }
        }
        __syncthreads();
    }

    const float* b1e = b1 + (size_t)e * 2 * FF;
    #pragma unroll
    for (int i = 0; i < 4; i++) {
        int m = m0 + ty * 4 + i;
        if (m >= cnt) continue;
        float* orow = g_act + ((size_t)e * MAXT + m) * FF;
        #pragma unroll
        for (int j = 0; j < 4; j++) {
            int n = n0 + tx * 4 + j;
            float h1 = acc1[i][j] + b1e[n];
            float h2 = acc2[i][j] + b1e[FF + n];
            float sil = h2 / (1.f + __expf(-h2));
            orow[n] = h1 * sil;
        }
    }
}

// --------------------------------------------------------------------------
// GEMM2: y[m, n] = a @ W2e.T + b2e ; scatter-add w * y into out rows
__global__ __launch_bounds__(256) void gemm2_k(const float* __restrict__ W2,
                                               const float* __restrict__ b2,
                                               float* __restrict__ out) {
    int e   = blockIdx.z;
    int cnt = g_cnt[e];
    int m0  = blockIdx.y * TM;
    if (m0 >= cnt) return;
    int n0  = blockIdx.x * TN;

    __shared__ float As[TK][TM];
    __shared__ float Bs[TK][TN];
    __shared__ int   toks[TM];
    __shared__ float wts[TM];

    int tid = threadIdx.x;
    if (tid < TM) {
        int m = m0 + tid;
        toks[tid] = (m < cnt) ? g_tok[e * MAXT + m] : -1;
        wts[tid]  = (m < cnt) ? g_wt[e * MAXT + m] : 0.f;
    }
    __syncthreads();

    const float* W2e = W2 + (size_t)e * DM * FF;
    int r  = tid >> 2, q = tid & 3;
    int tx = tid & 15, ty = tid >> 4;

    float acc[4][4];
    #pragma unroll
    for (int i = 0; i < 4; i++)
        #pragma unroll
        for (int j = 0; j < 4; j++) acc[i][j] = 0.f;

    const float* arow = g_act + ((size_t)e * MAXT + m0 + r) * FF;
    const float* brow = W2e + (size_t)(n0 + r) * FF;

    for (int k0 = 0; k0 < FF; k0 += TK) {
        float4 va = *(const float4*)(arow + k0 + q * 4);
        float4 vb = *(const float4*)(brow + k0 + q * 4);
        As[q*4+0][r] = va.x; As[q*4+1][r] = va.y; As[q*4+2][r] = va.z; As[q*4+3][r] = va.w;
        Bs[q*4+0][r] = vb.x; Bs[q*4+1][r] = vb.y; Bs[q*4+2][r] = vb.z; Bs[q*4+3][r] = vb.w;
        __syncthreads();
        #pragma unroll
        for (int kk = 0; kk < TK; kk++) {
            float4 a4 = *(const float4*)&As[kk][ty * 4];
            float4 b4 = *(const float4*)&Bs[kk][tx * 4];
            float av[4] = {a4.x, a4.y, a4.z, a4.w};
            float bv[4] = {b4.x, b4.y, b4.z, b4.w};
            #pragma unroll
            for (int i = 0; i < 4; i++)
                #pragma unroll
                for (int j = 0; j < 4; j++)
                    acc[i][j] += av[i] * bv[j];
        }
        __syncthreads();
    }

    const float* b2e = b2 + (size_t)e * DM;
    #pragma unroll
    for (int i = 0; i < 4; i++) {
        int mi = ty * 4 + i;
        int m  = m0 + mi;
        if (m >= cnt) continue;
        int   tok = toks[mi];
        float w   = wts[mi];
        float* dst = out + (size_t)tok * DM;
        #pragma unroll
        for (int j = 0; j < 4; j++) {
            int n = n0 + tx * 4 + j;
            atomicAdd(dst + n, w * (acc[i][j] + b2e[n]));
        }
    }
}

// --------------------------------------------------------------------------
extern "C" void kernel_launch(void* const* d_in, const int* in_sizes, int n_in,
                              void* d_out, int out_size) {
    const float* x    = (const float*)d_in[0];
    const float* Wr   = (const float*)d_in[1];
    const float* temp = (const float*)d_in[2];
    const float* W1   = (const float*)d_in[3];
    const float* b1   = (const float*)d_in[4];
    const float* W2   = (const float*)d_in[5];
    const float* b2   = (const float*)d_in[6];
    float* out = (float*)d_out;

    int T = in_sizes[0] / DM;           // 4096 tokens

    cudaMemsetAsync(d_out, 0, (size_t)out_size * sizeof(float), 0);
    init_k<<<1, 32>>>();
    router_k<<<T, 256>>>(x, Wr, temp);

    dim3 g1(FF / TN, (T + TM - 1) / TM, NE);
    gemm1_k<<<g1, 256>>>(x, W1, b1);

    dim3 g2(DM / TN, (T + TM - 1) / TM, NE);
    gemm2_k<<<g2, 256>>>(W2, b2, out);
}

// round 3
// speedup vs baseline: 2.8922x; 2.8922x over previous
#include <cuda_runtime.h>
#include <cstdint>

#define DM   1024
#define NE   8
#define FF   2048
#define MAXT 4096
#define TKC  32
#define SST  36          // smem row stride (words): 32 + 4 pad -> conflict-free frags

// -------- persistent device scratch (no dynamic alloc allowed) -------------
__device__ int   g_cnt[NE];
__device__ int   g_tok[NE * MAXT];
__device__ float g_wt [NE * MAXT];
__device__ float g_act[(size_t)NE * MAXT * FF];

// ---------------------------------------------------------------------------
__device__ __forceinline__ uint32_t f2tf(float f) {
    uint32_t r; asm("cvt.rna.tf32.f32 %0, %1;" : "=r"(r) : "f"(f)); return r;
}
__device__ __forceinline__ void mma8(float c[4], const uint32_t a[4], const uint32_t b[2]) {
    asm volatile(
        "mma.sync.aligned.m16n8k8.row.col.f32.tf32.tf32.f32 "
        "{%0,%1,%2,%3}, {%4,%5,%6,%7}, {%8,%9}, {%0,%1,%2,%3};"
        : "+f"(c[0]), "+f"(c[1]), "+f"(c[2]), "+f"(c[3])
        : "r"(a[0]), "r"(a[1]), "r"(a[2]), "r"(a[3]), "r"(b[0]), "r"(b[1]));
}

// ---------------------------------------------------------------------------
__global__ void init_k() { if (threadIdx.x < NE) g_cnt[threadIdx.x] = 0; }

__global__ void router_k(const float* __restrict__ x,
                         const float* __restrict__ Wr,
                         const float* __restrict__ temp) {
    __shared__ float xs[DM];
    __shared__ float lg[NE];
    int t = blockIdx.x;
    const float* xr = x + (size_t)t * DM;
    for (int i = threadIdx.x; i < DM; i += blockDim.x) xs[i] = xr[i];
    __syncthreads();
    int w = threadIdx.x >> 5, lane = threadIdx.x & 31;
    if (w < NE) {
        const float* wr = Wr + (size_t)w * DM;
        float s = 0.f;
        for (int i = lane; i < DM; i += 32) s += xs[i] * wr[i];
        #pragma unroll
        for (int o = 16; o; o >>= 1) s += __shfl_xor_sync(0xffffffffu, s, o);
        if (lane == 0) lg[w] = s;
    }
    __syncthreads();
    if (threadIdx.x == 0) {
        float it = 1.f / temp[0];
        float l[NE];
        #pragma unroll
        for (int e = 0; e < NE; e++) l[e] = lg[e] * it;
        int i0 = 0;
        #pragma unroll
        for (int e = 1; e < NE; e++) if (l[e] > l[i0]) i0 = e;
        int i1 = (i0 == 0) ? 1 : 0;
        #pragma unroll
        for (int e = 0; e < NE; e++) if (e != i0 && l[e] > l[i1]) i1 = e;
        float m  = l[i0];
        float e0 = __expf(l[i0] - m), e1 = __expf(l[i1] - m);
        float inv = 1.f / (e0 + e1);
        int s0 = atomicAdd(&g_cnt[i0], 1);
        g_tok[i0 * MAXT + s0] = t;  g_wt[i0 * MAXT + s0] = e0 * inv;
        int s1 = atomicAdd(&g_cnt[i1], 1);
        g_tok[i1 * MAXT + s1] = t;  g_wt[i1 * MAXT + s1] = e1 * inv;
    }
}

// ---------------------------------------------------------------------------
// GEMM1: tile 128(M) x 64(N) over BOTH W1 halves; fused SwiGLU -> g_act
// 8 warps: wm in {0,64}, wn in {0,16,32,48}; warp tile 64x16 per half
__global__ __launch_bounds__(256, 2) void gemm1_k(const float* __restrict__ x,
                                                  const float* __restrict__ W1,
                                                  const float* __restrict__ b1) {
    int e   = blockIdx.z;
    int cnt = g_cnt[e];
    int m0  = blockIdx.y * 128;
    if (m0 >= cnt) return;
    int n0  = blockIdx.x * 64;

    __shared__ uint32_t As[128 * SST];
    __shared__ uint32_t Bs[2 * 64 * SST];
    __shared__ int toks[128];

    int tid = threadIdx.x, wid = tid >> 5, lane = tid & 31;
    int g = lane >> 2, tig = lane & 3;
    int wm = (wid & 1) * 64, wn = (wid >> 1) * 16;

    if (tid < 128) { int m = m0 + tid; toks[tid] = (m < cnt) ? g_tok[e * MAXT + m] : -1; }
    __syncthreads();

    const float* W1e = W1 + (size_t)e * (2 * FF) * DM;

    float acc[2][4][2][4];
    #pragma unroll
    for (int h = 0; h < 2; h++)
        #pragma unroll
        for (int mt = 0; mt < 4; mt++)
            #pragma unroll
            for (int nt = 0; nt < 2; nt++)
                #pragma unroll
                for (int j = 0; j < 4; j++) acc[h][mt][nt][j] = 0.f;

    for (int k0 = 0; k0 < DM; k0 += TKC) {
        #pragma unroll
        for (int i = 0; i < 4; i++) {                 // A: 128 rows x 8 quads
            int idx = tid + i * 256, r = idx >> 3, q = idx & 7;
            int tok = toks[r];
            float4 v = (tok >= 0) ? *(const float4*)(x + (size_t)tok * DM + k0 + q * 4)
                                  : make_float4(0.f, 0.f, 0.f, 0.f);
            uint32_t* p = &As[r * SST + q * 4];
            p[0] = f2tf(v.x); p[1] = f2tf(v.y); p[2] = f2tf(v.z); p[3] = f2tf(v.w);
        }
        #pragma unroll
        for (int i = 0; i < 4; i++) {                 // B: 2 halves x 64 rows x 8 quads
            int idx = tid + i * 256, h = idx >> 9, rem = idx & 511;
            int r = rem >> 3, q = rem & 7;
            float4 v = *(const float4*)(W1e + (size_t)(h * FF + n0 + r) * DM + k0 + q * 4);
            uint32_t* p = &Bs[(h * 64 + r) * SST + q * 4];
            p[0] = f2tf(v.x); p[1] = f2tf(v.y); p[2] = f2tf(v.z); p[3] = f2tf(v.w);
        }
        __syncthreads();
        #pragma unroll
        for (int kk = 0; kk < TKC; kk += 8) {
            uint32_t af[4][4];
            #pragma unroll
            for (int mt = 0; mt < 4; mt++) {
                int rb = wm + mt * 16;
                af[mt][0] = As[(rb + g)     * SST + kk + tig];
                af[mt][1] = As[(rb + g + 8) * SST + kk + tig];
                af[mt][2] = As[(rb + g)     * SST + kk + tig + 4];
                af[mt][3] = As[(rb + g + 8) * SST + kk + tig + 4];
            }
            uint32_t bf[2][2][2];
            #pragma unroll
            for (int h = 0; h < 2; h++)
                #pragma unroll
                for (int nt = 0; nt < 2; nt++) {
                    int rb = h * 64 + wn + nt * 8;
                    bf[h][nt][0] = Bs[(rb + g) * SST + kk + tig];
                    bf[h][nt][1] = Bs[(rb + g) * SST + kk + tig + 4];
                }
            #pragma unroll
            for (int h = 0; h < 2; h++)
                #pragma unroll
                for (int mt = 0; mt < 4; mt++)
                    #pragma unroll
                    for (int nt = 0; nt < 2; nt++)
                        mma8(acc[h][mt][nt], af[mt], bf[h][nt]);
        }
        __syncthreads();
    }

    const float* b1e  = b1 + (size_t)e * 2 * FF;
    float*       acte = g_act + (size_t)e * MAXT * FF;
    #pragma unroll
    for (int mt = 0; mt < 4; mt++)
        #pragma unroll
        for (int rr = 0; rr < 2; rr++) {
            int mg = m0 + wm + mt * 16 + g + rr * 8;
            if (mg >= cnt) continue;
            float* orow = acte + (size_t)mg * FF;
            #pragma unroll
            for (int nt = 0; nt < 2; nt++) {
                int col = n0 + wn + nt * 8 + tig * 2;
                float h1a = acc[0][mt][nt][rr * 2 + 0] + b1e[col];
                float h1b = acc[0][mt][nt][rr * 2 + 1] + b1e[col + 1];
                float h2a = acc[1][mt][nt][rr * 2 + 0] + b1e[FF + col];
                float h2b = acc[1][mt][nt][rr * 2 + 1] + b1e[FF + col + 1];
                float2 o;
                o.x = h1a * h2a / (1.f + __expf(-h2a));
                o.y = h1b * h2b / (1.f + __expf(-h2b));
                *(float2*)(orow + col) = o;
            }
        }
}

// ---------------------------------------------------------------------------
// GEMM2: tile 128(M) x 128(N); gated atomic scatter into out
// 8 warps: wm in {0,64}, wn in {0,32,64,96}; warp tile 64x32
__global__ __launch_bounds__(256, 2) void gemm2_k(const float* __restrict__ W2,
                                                  const float* __restrict__ b2,
                                                  float* __restrict__ out) {
    int e   = blockIdx.z;
    int cnt = g_cnt[e];
    int m0  = blockIdx.y * 128;
    if (m0 >= cnt) return;
    int n0  = blockIdx.x * 128;

    __shared__ uint32_t As[128 * SST];
    __shared__ uint32_t Bs[128 * SST];
    __shared__ int   toks[128];
    __shared__ float wts[128];

    int tid = threadIdx.x, wid = tid >> 5, lane = tid & 31;
    int g = lane >> 2, tig = lane & 3;
    int wm = (wid & 1) * 64, wn = (wid >> 1) * 32;

    if (tid < 128) {
        int m = m0 + tid;
        toks[tid] = (m < cnt) ? g_tok[e * MAXT + m] : -1;
        wts[tid]  = (m < cnt) ? g_wt[e * MAXT + m] : 0.f;
    }
    __syncthreads();

    const float* W2e  = W2 + (size_t)e * DM * FF;
    const float* acte = g_act + (size_t)e * MAXT * FF;

    float acc[4][4][4];
    #pragma unroll
    for (int mt = 0; mt < 4; mt++)
        #pragma unroll
        for (int nt = 0; nt < 4; nt++)
            #pragma unroll
            for (int j = 0; j < 4; j++) acc[mt][nt][j] = 0.f;

    for (int k0 = 0; k0 < FF; k0 += TKC) {
        #pragma unroll
        for (int i = 0; i < 4; i++) {                 // A rows from act
            int idx = tid + i * 256, r = idx >> 3, q = idx & 7;
            float4 v = (m0 + r < cnt)
                ? *(const float4*)(acte + (size_t)(m0 + r) * FF + k0 + q * 4)
                : make_float4(0.f, 0.f, 0.f, 0.f);
            uint32_t* p = &As[r * SST + q * 4];
            p[0] = f2tf(v.x); p[1] = f2tf(v.y); p[2] = f2tf(v.z); p[3] = f2tf(v.w);
        }
        #pragma unroll
        for (int i = 0; i < 4; i++) {                 // B rows from W2
            int idx = tid + i * 256, r = idx >> 3, q = idx & 7;
            float4 v = *(const float4*)(W2e + (size_t)(n0 + r) * FF + k0 + q * 4);
            uint32_t* p = &Bs[r * SST + q * 4];
            p[0] = f2tf(v.x); p[1] = f2tf(v.y); p[2] = f2tf(v.z); p[3] = f2tf(v.w);
        }
        __syncthreads();
        #pragma unroll
        for (int kk = 0; kk < TKC; kk += 8) {
            uint32_t af[4][4];
            #pragma unroll
            for (int mt = 0; mt < 4; mt++) {
                int rb = wm + mt * 16;
                af[mt][0] = As[(rb + g)     * SST + kk + tig];
                af[mt][1] = As[(rb + g + 8) * SST + kk + tig];
                af[mt][2] = As[(rb + g)     * SST + kk + tig + 4];
                af[mt][3] = As[(rb + g + 8) * SST + kk + tig + 4];
            }
            uint32_t bf[4][2];
            #pragma unroll
            for (int nt = 0; nt < 4; nt++) {
                int rb = wn + nt * 8;
                bf[nt][0] = Bs[(rb + g) * SST + kk + tig];
                bf[nt][1] = Bs[(rb + g) * SST + kk + tig + 4];
            }
            #pragma unroll
            for (int mt = 0; mt < 4; mt++)
                #pragma unroll
                for (int nt = 0; nt < 4; nt++)
                    mma8(acc[mt][nt], af[mt], bf[nt]);
        }
        __syncthreads();
    }

    const float* b2e = b2 + (size_t)e * DM;
    #pragma unroll
    for (int mt = 0; mt < 4; mt++)
        #pragma unroll
        for (int rr = 0; rr < 2; rr++) {
            int lm = wm + mt * 16 + g + rr * 8;
            int mg = m0 + lm;
            if (mg >= cnt) continue;
            int   tok = toks[lm];
            float w   = wts[lm];
            float* dst = out + (size_t)tok * DM;
            #pragma unroll
            for (int nt = 0; nt < 4; nt++) {
                int col = n0 + wn + nt * 8 + tig * 2;
                atomicAdd(dst + col,     w * (acc[mt][nt][rr * 2 + 0] + b2e[col]));
                atomicAdd(dst + col + 1, w * (acc[mt][nt][rr * 2 + 1] + b2e[col + 1]));
            }
        }
}

// ---------------------------------------------------------------------------
extern "C" void kernel_launch(void* const* d_in, const int* in_sizes, int n_in,
                              void* d_out, int out_size) {
    const float* x    = (const float*)d_in[0];
    const float* Wr   = (const float*)d_in[1];
    const float* temp = (const float*)d_in[2];
    const float* W1   = (const float*)d_in[3];
    const float* b1   = (const float*)d_in[4];
    const float* W2   = (const float*)d_in[5];
    const float* b2   = (const float*)d_in[6];
    float* out = (float*)d_out;

    int T = in_sizes[0] / DM;
    int MB = (T + 127) / 128;

    cudaMemsetAsync(d_out, 0, (size_t)out_size * sizeof(float), 0);
    init_k<<<1, 32>>>();
    router_k<<<T, 256>>>(x, Wr, temp);

    dim3 g1(FF / 64, MB, NE);
    gemm1_k<<<g1, 256>>>(x, W1, b1);

    dim3 g2(DM / 128, MB, NE);
    gemm2_k<<<g2, 256>>>(W2, b2, out);
}

// round 4
// speedup vs baseline: 3.8477x; 1.3304x over previous
#include <cuda_runtime.h>
#include <cstdint>

#define DM   1024
#define NE   8
#define FF   2048
#define MAXT 4096
#define TKC  32
#define SST  36            // smem row stride in words (32 + 4 pad)
#define STGW (256 * SST)   // words per stage (A 128 rows + B 128 rows)
#define STGB (STGW * 4)    // bytes per stage = 36864

// -------- persistent device scratch (no dynamic alloc allowed) -------------
__device__ int      g_cnt[NE];
__device__ int      g_tok[NE * MAXT];
__device__ float    g_wt [NE * MAXT];
__device__ float    g_act[(size_t)NE * MAXT * FF];          // tf32-rounded values
__device__ uint32_t g_xtf [(size_t)MAXT * DM];
__device__ uint32_t g_w1tf[(size_t)NE * 2 * FF * DM];
__device__ uint32_t g_w2tf[(size_t)NE * DM * FF];

// ---------------------------------------------------------------------------
__device__ __forceinline__ uint32_t f2tf(float f) {
    uint32_t r; asm("cvt.rna.tf32.f32 %0, %1;" : "=r"(r) : "f"(f)); return r;
}
__device__ __forceinline__ uint32_t smem_u32(const void* p) {
    uint32_t a;
    asm("{ .reg .u64 t; cvta.to.shared.u64 t, %1; cvt.u32.u64 %0, t; }" : "=r"(a) : "l"(p));
    return a;
}
__device__ __forceinline__ void cpa16(uint32_t dst, const void* src, int sz) {
    asm volatile("cp.async.cg.shared.global [%0], [%1], 16, %2;"
                 :: "r"(dst), "l"(src), "r"(sz) : "memory");
}
#define CP_COMMIT() asm volatile("cp.async.commit_group;" ::: "memory")
#define CP_WAIT1()  asm volatile("cp.async.wait_group 1;" ::: "memory")
#define CP_WAIT0()  asm volatile("cp.async.wait_group 0;" ::: "memory")

__device__ __forceinline__ void mma8(float c[4], const uint32_t a[4], const uint32_t b[2]) {
    asm volatile(
        "mma.sync.aligned.m16n8k8.row.col.f32.tf32.tf32.f32 "
        "{%0,%1,%2,%3}, {%4,%5,%6,%7}, {%8,%9}, {%0,%1,%2,%3};"
        : "+f"(c[0]), "+f"(c[1]), "+f"(c[2]), "+f"(c[3])
        : "r"(a[0]), "r"(a[1]), "r"(a[2]), "r"(a[3]), "r"(b[0]), "r"(b[1]));
}

// ---------------------------------------------------------------------------
__global__ void init_k() { if (threadIdx.x < NE) g_cnt[threadIdx.x] = 0; }

__global__ void cvt_k(const float* __restrict__ src, uint32_t* __restrict__ dst, int n4) {
    int i = blockIdx.x * blockDim.x + threadIdx.x;
    int stride = gridDim.x * blockDim.x;
    for (; i < n4; i += stride) {
        float4 v = ((const float4*)src)[i];
        uint4 o;
        o.x = f2tf(v.x); o.y = f2tf(v.y); o.z = f2tf(v.z); o.w = f2tf(v.w);
        ((uint4*)dst)[i] = o;
    }
}

__global__ void router_k(const float* __restrict__ x,
                         const float* __restrict__ Wr,
                         const float* __restrict__ temp) {
    __shared__ float xs[DM];
    __shared__ float lg[NE];
    int t = blockIdx.x;
    const float* xr = x + (size_t)t * DM;
    for (int i = threadIdx.x; i < DM; i += blockDim.x) xs[i] = xr[i];
    __syncthreads();
    int w = threadIdx.x >> 5, lane = threadIdx.x & 31;
    if (w < NE) {
        const float* wr = Wr + (size_t)w * DM;
        float s = 0.f;
        for (int i = lane; i < DM; i += 32) s += xs[i] * wr[i];
        #pragma unroll
        for (int o = 16; o; o >>= 1) s += __shfl_xor_sync(0xffffffffu, s, o);
        if (lane == 0) lg[w] = s;
    }
    __syncthreads();
    if (threadIdx.x == 0) {
        float it = 1.f / temp[0];
        float l[NE];
        #pragma unroll
        for (int e = 0; e < NE; e++) l[e] = lg[e] * it;
        int i0 = 0;
        #pragma unroll
        for (int e = 1; e < NE; e++) if (l[e] > l[i0]) i0 = e;
        int i1 = (i0 == 0) ? 1 : 0;
        #pragma unroll
        for (int e = 0; e < NE; e++) if (e != i0 && l[e] > l[i1]) i1 = e;
        float m  = l[i0];
        float e0 = __expf(l[i0] - m), e1 = __expf(l[i1] - m);
        float inv = 1.f / (e0 + e1);
        int s0 = atomicAdd(&g_cnt[i0], 1);
        g_tok[i0 * MAXT + s0] = t;  g_wt[i0 * MAXT + s0] = e0 * inv;
        int s1 = atomicAdd(&g_cnt[i1], 1);
        g_tok[i1 * MAXT + s1] = t;  g_wt[i1 * MAXT + s1] = e1 * inv;
    }
}

// ---------------------------------------------------------------------------
// GEMM1: tile 128(M) x 64(N) over BOTH W1 halves; fused SwiGLU -> g_act (tf32)
__global__ __launch_bounds__(256, 2) void gemm1_k(const float* __restrict__ b1) {
    int e   = blockIdx.z;
    int cnt = g_cnt[e];
    int m0  = blockIdx.y * 128;
    if (m0 >= cnt) return;
    int n0  = blockIdx.x * 64;

    extern __shared__ uint32_t dynw[];
    uint32_t sb = smem_u32(dynw);
    __shared__ int toks[128];

    int tid = threadIdx.x, wid = tid >> 5, lane = tid & 31;
    int g = lane >> 2, tig = lane & 3;
    int wm = (wid & 1) * 64, wn = (wid >> 1) * 16;

    if (tid < 128) { int m = m0 + tid; toks[tid] = (m < cnt) ? g_tok[e * MAXT + m] : -1; }
    __syncthreads();

    const uint32_t* W1e = g_w1tf + (size_t)e * (2 * FF) * DM;

    float acc[2][4][2][4];
    #pragma unroll
    for (int h = 0; h < 2; h++)
        #pragma unroll
        for (int mt = 0; mt < 4; mt++)
            #pragma unroll
            for (int nt = 0; nt < 2; nt++)
                #pragma unroll
                for (int j = 0; j < 4; j++) acc[h][mt][nt][j] = 0.f;

    const int NC = DM / TKC;    // 32 chunks

    #define ISSUE1(c, s) do {                                                     \
        int k0_ = (c) * TKC;                                                      \
        uint32_t ab_ = sb + (uint32_t)(s) * STGB;                                 \
        _Pragma("unroll")                                                         \
        for (int i_ = 0; i_ < 4; i_++) {                                          \
            int idx_ = tid + i_ * 256, r_ = idx_ >> 3, q_ = idx_ & 7;             \
            int tok_ = toks[r_];                                                  \
            const uint32_t* src_ = g_xtf + (size_t)(tok_ < 0 ? 0 : tok_) * DM     \
                                   + k0_ + q_ * 4;                                \
            cpa16(ab_ + (uint32_t)(r_ * SST + q_ * 4) * 4, src_,                  \
                  tok_ >= 0 ? 16 : 0);                                            \
        }                                                                         \
        uint32_t bb_ = ab_ + 128u * SST * 4u;                                     \
        _Pragma("unroll")                                                         \
        for (int i_ = 0; i_ < 4; i_++) {                                          \
            int idx_ = tid + i_ * 256, h_ = idx_ >> 9, rem_ = idx_ & 511;         \
            int r_ = rem_ >> 3, q_ = rem_ & 7;                                    \
            const uint32_t* src_ = W1e + (size_t)(h_ * FF + n0 + r_) * DM         \
                                   + k0_ + q_ * 4;                                \
            cpa16(bb_ + (uint32_t)((h_ * 64 + r_) * SST + q_ * 4) * 4, src_, 16); \
        }                                                                         \
        CP_COMMIT();                                                              \
    } while (0)

    ISSUE1(0, 0);
    ISSUE1(1, 1);

    for (int c = 0; c < NC; ++c) {
        int s = c & 1;
        if (c + 1 < NC) CP_WAIT1(); else CP_WAIT0();
        __syncthreads();
        const uint32_t* SA = dynw + s * STGW;
        const uint32_t* SB = SA + 128 * SST;
        #pragma unroll
        for (int kk = 0; kk < TKC; kk += 8) {
            uint32_t af[4][4];
            #pragma unroll
            for (int mt = 0; mt < 4; mt++) {
                int rb = wm + mt * 16;
                af[mt][0] = SA[(rb + g)     * SST + kk + tig];
                af[mt][1] = SA[(rb + g + 8) * SST + kk + tig];
                af[mt][2] = SA[(rb + g)     * SST + kk + tig + 4];
                af[mt][3] = SA[(rb + g + 8) * SST + kk + tig + 4];
            }
            uint32_t bf[2][2][2];
            #pragma unroll
            for (int h = 0; h < 2; h++)
                #pragma unroll
                for (int nt = 0; nt < 2; nt++) {
                    int rb = h * 64 + wn + nt * 8;
                    bf[h][nt][0] = SB[(rb + g) * SST + kk + tig];
                    bf[h][nt][1] = SB[(rb + g) * SST + kk + tig + 4];
                }
            #pragma unroll
            for (int h = 0; h < 2; h++)
                #pragma unroll
                for (int mt = 0; mt < 4; mt++)
                    #pragma unroll
                    for (int nt = 0; nt < 2; nt++)
                        mma8(acc[h][mt][nt], af[mt], bf[h][nt]);
        }
        __syncthreads();
        if (c + 2 < NC) ISSUE1(c + 2, s);
    }

    const float* b1e  = b1 + (size_t)e * 2 * FF;
    float*       acte = g_act + (size_t)e * MAXT * FF;
    #pragma unroll
    for (int mt = 0; mt < 4; mt++)
        #pragma unroll
        for (int rr = 0; rr < 2; rr++) {
            int mg = m0 + wm + mt * 16 + g + rr * 8;
            if (mg >= cnt) continue;
            float* orow = acte + (size_t)mg * FF;
            #pragma unroll
            for (int nt = 0; nt < 2; nt++) {
                int col = n0 + wn + nt * 8 + tig * 2;
                float h1a = acc[0][mt][nt][rr * 2 + 0] + b1e[col];
                float h1b = acc[0][mt][nt][rr * 2 + 1] + b1e[col + 1];
                float h2a = acc[1][mt][nt][rr * 2 + 0] + b1e[FF + col];
                float h2b = acc[1][mt][nt][rr * 2 + 1] + b1e[FF + col + 1];
                float2 o;
                o.x = __uint_as_float(f2tf(h1a * h2a / (1.f + __expf(-h2a))));
                o.y = __uint_as_float(f2tf(h1b * h2b / (1.f + __expf(-h2b))));
                *(float2*)(orow + col) = o;
            }
        }
    #undef ISSUE1
}

// ---------------------------------------------------------------------------
// GEMM2: tile 128(M) x 128(N); gated atomic scatter into out
__global__ __launch_bounds__(256, 2) void gemm2_k(const float* __restrict__ b2,
                                                  float* __restrict__ out) {
    int e   = blockIdx.z;
    int cnt = g_cnt[e];
    int m0  = blockIdx.y * 128;
    if (m0 >= cnt) return;
    int n0  = blockIdx.x * 128;

    extern __shared__ uint32_t dynw[];
    uint32_t sb = smem_u32(dynw);
    __shared__ int   toks[128];
    __shared__ float wts[128];

    int tid = threadIdx.x, wid = tid >> 5, lane = tid & 31;
    int g = lane >> 2, tig = lane & 3;
    int wm = (wid & 1) * 64, wn = (wid >> 1) * 32;

    if (tid < 128) {
        int m = m0 + tid;
        toks[tid] = (m < cnt) ? g_tok[e * MAXT + m] : -1;
        wts[tid]  = (m < cnt) ? g_wt[e * MAXT + m] : 0.f;
    }
    __syncthreads();

    const uint32_t* W2e  = g_w2tf + (size_t)e * DM * FF;
    const float*    acte = g_act + (size_t)e * MAXT * FF;

    float acc[4][4][4];
    #pragma unroll
    for (int mt = 0; mt < 4; mt++)
        #pragma unroll
        for (int nt = 0; nt < 4; nt++)
            #pragma unroll
            for (int j = 0; j < 4; j++) acc[mt][nt][j] = 0.f;

    const int NC = FF / TKC;    // 64 chunks

    #define ISSUE2(c, s) do {                                                     \
        int k0_ = (c) * TKC;                                                      \
        uint32_t ab_ = sb + (uint32_t)(s) * STGB;                                 \
        _Pragma("unroll")                                                         \
        for (int i_ = 0; i_ < 4; i_++) {                                          \
            int idx_ = tid + i_ * 256, r_ = idx_ >> 3, q_ = idx_ & 7;             \
            int ok_ = (m0 + r_ < cnt);                                            \
            const float* src_ = acte + (size_t)(m0 + (ok_ ? r_ : 0)) * FF         \
                                + k0_ + q_ * 4;                                   \
            cpa16(ab_ + (uint32_t)(r_ * SST + q_ * 4) * 4, src_, ok_ ? 16 : 0);   \
        }                                                                         \
        uint32_t bb_ = ab_ + 128u * SST * 4u;                                     \
        _Pragma("unroll")                                                         \
        for (int i_ = 0; i_ < 4; i_++) {                                          \
            int idx_ = tid + i_ * 256, r_ = idx_ >> 3, q_ = idx_ & 7;             \
            const uint32_t* src_ = W2e + (size_t)(n0 + r_) * FF + k0_ + q_ * 4;   \
            cpa16(bb_ + (uint32_t)(r_ * SST + q_ * 4) * 4, src_, 16);             \
        }                                                                         \
        CP_COMMIT();                                                              \
    } while (0)

    ISSUE2(0, 0);
    ISSUE2(1, 1);

    for (int c = 0; c < NC; ++c) {
        int s = c & 1;
        if (c + 1 < NC) CP_WAIT1(); else CP_WAIT0();
        __syncthreads();
        const uint32_t* SA = dynw + s * STGW;
        const uint32_t* SB = SA + 128 * SST;
        #pragma unroll
        for (int kk = 0; kk < TKC; kk += 8) {
            uint32_t af[4][4];
            #pragma unroll
            for (int mt = 0; mt < 4; mt++) {
                int rb = wm + mt * 16;
                af[mt][0] = SA[(rb + g)     * SST + kk + tig];
                af[mt][1] = SA[(rb + g + 8) * SST + kk + tig];
                af[mt][2] = SA[(rb + g)     * SST + kk + tig + 4];
                af[mt][3] = SA[(rb + g + 8) * SST + kk + tig + 4];
            }
            uint32_t bf[4][2];
            #pragma unroll
            for (int nt = 0; nt < 4; nt++) {
                int rb = wn + nt * 8;
                bf[nt][0] = SB[(rb + g) * SST + kk + tig];
                bf[nt][1] = SB[(rb + g) * SST + kk + tig + 4];
            }
            #pragma unroll
            for (int mt = 0; mt < 4; mt++)
                #pragma unroll
                for (int nt = 0; nt < 4; nt++)
                    mma8(acc[mt][nt], af[mt], bf[nt]);
        }
        __syncthreads();
        if (c + 2 < NC) ISSUE2(c + 2, s);
    }

    const float* b2e = b2 + (size_t)e * DM;
    #pragma unroll
    for (int mt = 0; mt < 4; mt++)
        #pragma unroll
        for (int rr = 0; rr < 2; rr++) {
            int lm = wm + mt * 16 + g + rr * 8;
            int mg = m0 + lm;
            if (mg >= cnt) continue;
            int   tok = toks[lm];
            float w   = wts[lm];
            float* dst = out + (size_t)tok * DM;
            #pragma unroll
            for (int nt = 0; nt < 4; nt++) {
                int col = n0 + wn + nt * 8 + tig * 2;
                atomicAdd(dst + col,     w * (acc[mt][nt][rr * 2 + 0] + b2e[col]));
                atomicAdd(dst + col + 1, w * (acc[mt][nt][rr * 2 + 1] + b2e[col + 1]));
            }
        }
    #undef ISSUE2
}

// ---------------------------------------------------------------------------
extern "C" void kernel_launch(void* const* d_in, const int* in_sizes, int n_in,
                              void* d_out, int out_size) {
    const float* x    = (const float*)d_in[0];
    const float* Wr   = (const float*)d_in[1];
    const float* temp = (const float*)d_in[2];
    const float* W1   = (const float*)d_in[3];
    const float* b1   = (const float*)d_in[4];
    const float* W2   = (const float*)d_in[5];
    const float* b2   = (const float*)d_in[6];
    float* out = (float*)d_out;

    int T  = in_sizes[0] / DM;
    int MB = (T + 127) / 128;

    static uint32_t *p_xtf = nullptr, *p_w1 = nullptr, *p_w2 = nullptr;
    if (!p_xtf) {
        cudaGetSymbolAddress((void**)&p_xtf, g_xtf);
        cudaGetSymbolAddress((void**)&p_w1, g_w1tf);
        cudaGetSymbolAddress((void**)&p_w2, g_w2tf);
    }

    const int DSM = 2 * STGB;
    cudaFuncSetAttribute(gemm1_k, cudaFuncAttributeMaxDynamicSharedMemorySize, DSM);
    cudaFuncSetAttribute(gemm2_k, cudaFuncAttributeMaxDynamicSharedMemorySize, DSM);

    cudaMemsetAsync(d_out, 0, (size_t)out_size * sizeof(float), 0);
    init_k<<<1, 32>>>();

    cvt_k<<<1184, 256>>>(x,  p_xtf, T * DM / 4);
    cvt_k<<<1184, 256>>>(W1, p_w1, NE * 2 * FF * DM / 4);
    cvt_k<<<1184, 256>>>(W2, p_w2, NE * DM * FF / 4);
    router_k<<<T, 256>>>(x, Wr, temp);

    dim3 g1(FF / 64, MB, NE);
    gemm1_k<<<g1, 256, DSM>>>(b1);

    dim3 g2(DM / 128, MB, NE);
    gemm2_k<<<g2, 256, DSM>>>(b2, out);
}

// round 5
// speedup vs baseline: 3.9113x; 1.0165x over previous
#include <cuda_runtime.h>
#include <cstdint>

#define DM   1024
#define NE   8
#define FF   2048
#define MAXT 4096
#define TKC  32
#define SST  36            // smem row stride in words (32 + 4 pad)
#define STGW (256 * SST)   // words per stage (A 128 rows + B 128 rows)
#define STGB (STGW * 4)    // bytes per stage = 36864

// -------- persistent device scratch (no dynamic alloc allowed) -------------
__device__ int   g_cnt[NE];
__device__ int   g_tok[NE * MAXT];
__device__ float g_wt [NE * MAXT];
__device__ float g_act[(size_t)NE * MAXT * FF];

// ---------------------------------------------------------------------------
__device__ __forceinline__ uint32_t f2tf(float f) {
    uint32_t r; asm("cvt.rna.tf32.f32 %0, %1;" : "=r"(r) : "f"(f)); return r;
}
__device__ __forceinline__ uint32_t tfb(uint32_t raw) {   // raw fp32 bits -> tf32 bits
    return f2tf(__uint_as_float(raw));
}
__device__ __forceinline__ uint32_t smem_u32(const void* p) {
    uint32_t a;
    asm("{ .reg .u64 t; cvta.to.shared.u64 t, %1; cvt.u32.u64 %0, t; }" : "=r"(a) : "l"(p));
    return a;
}
__device__ __forceinline__ void cpa16(uint32_t dst, const void* src, int sz) {
    asm volatile("cp.async.cg.shared.global [%0], [%1], 16, %2;"
                 :: "r"(dst), "l"(src), "r"(sz) : "memory");
}
#define CP_COMMIT() asm volatile("cp.async.commit_group;" ::: "memory")
#define CP_WAIT1()  asm volatile("cp.async.wait_group 1;" ::: "memory")
#define CP_WAIT0()  asm volatile("cp.async.wait_group 0;" ::: "memory")

__device__ __forceinline__ void mma8(float c[4], const uint32_t a[4], const uint32_t b[2]) {
    asm volatile(
        "mma.sync.aligned.m16n8k8.row.col.f32.tf32.tf32.f32 "
        "{%0,%1,%2,%3}, {%4,%5,%6,%7}, {%8,%9}, {%0,%1,%2,%3};"
        : "+f"(c[0]), "+f"(c[1]), "+f"(c[2]), "+f"(c[3])
        : "r"(a[0]), "r"(a[1]), "r"(a[2]), "r"(a[3]), "r"(b[0]), "r"(b[1]));
}

// ---------------------------------------------------------------------------
__global__ void init_k() { if (threadIdx.x < NE) g_cnt[threadIdx.x] = 0; }

__global__ void router_k(const float* __restrict__ x,
                         const float* __restrict__ Wr,
                         const float* __restrict__ temp) {
    __shared__ float xs[DM];
    __shared__ float lg[NE];
    int t = blockIdx.x;
    const float* xr = x + (size_t)t * DM;
    for (int i = threadIdx.x; i < DM; i += blockDim.x) xs[i] = xr[i];
    __syncthreads();
    int w = threadIdx.x >> 5, lane = threadIdx.x & 31;
    if (w < NE) {
        const float* wr = Wr + (size_t)w * DM;
        float s = 0.f;
        for (int i = lane; i < DM; i += 32) s += xs[i] * wr[i];
        #pragma unroll
        for (int o = 16; o; o >>= 1) s += __shfl_xor_sync(0xffffffffu, s, o);
        if (lane == 0) lg[w] = s;
    }
    __syncthreads();
    if (threadIdx.x == 0) {
        float it = 1.f / temp[0];
        float l[NE];
        #pragma unroll
        for (int e = 0; e < NE; e++) l[e] = lg[e] * it;
        int i0 = 0;
        #pragma unroll
        for (int e = 1; e < NE; e++) if (l[e] > l[i0]) i0 = e;
        int i1 = (i0 == 0) ? 1 : 0;
        #pragma unroll
        for (int e = 0; e < NE; e++) if (e != i0 && l[e] > l[i1]) i1 = e;
        float m  = l[i0];
        float e0 = __expf(l[i0] - m), e1 = __expf(l[i1] - m);
        float inv = 1.f / (e0 + e1);
        int s0 = atomicAdd(&g_cnt[i0], 1);
        g_tok[i0 * MAXT + s0] = t;  g_wt[i0 * MAXT + s0] = e0 * inv;
        int s1 = atomicAdd(&g_cnt[i1], 1);
        g_tok[i1 * MAXT + s1] = t;  g_wt[i1 * MAXT + s1] = e1 * inv;
    }
}

// ---------------------------------------------------------------------------
// GEMM1: tile 128(M) x 64(N) over BOTH W1 halves; fused SwiGLU -> g_act
__global__ __launch_bounds__(256, 2) void gemm1_k(const float* __restrict__ x,
                                                  const float* __restrict__ W1,
                                                  const float* __restrict__ b1) {
    int e   = blockIdx.z;
    int cnt = g_cnt[e];
    int m0  = blockIdx.y * 128;
    if (m0 >= cnt) return;
    int n0  = blockIdx.x * 64;

    extern __shared__ uint32_t dynw[];
    uint32_t sb = smem_u32(dynw);
    __shared__ int toks[128];

    int tid = threadIdx.x, wid = tid >> 5, lane = tid & 31;
    int g = lane >> 2, tig = lane & 3;
    int wm = (wid & 1) * 64, wn = (wid >> 1) * 16;

    if (tid < 128) { int m = m0 + tid; toks[tid] = (m < cnt) ? g_tok[e * MAXT + m] : -1; }
    __syncthreads();

    const float* W1e = W1 + (size_t)e * (2 * FF) * DM;

    float acc[2][4][2][4];
    #pragma unroll
    for (int h = 0; h < 2; h++)
        #pragma unroll
        for (int mt = 0; mt < 4; mt++)
            #pragma unroll
            for (int nt = 0; nt < 2; nt++)
                #pragma unroll
                for (int j = 0; j < 4; j++) acc[h][mt][nt][j] = 0.f;

    const int NC = DM / TKC;    // 32 chunks

    #define ISSUE1(c, s) do {                                                     \
        int k0_ = (c) * TKC;                                                      \
        uint32_t ab_ = sb + (uint32_t)(s) * STGB;                                 \
        _Pragma("unroll")                                                         \
        for (int i_ = 0; i_ < 4; i_++) {                                          \
            int idx_ = tid + i_ * 256, r_ = idx_ >> 3, q_ = idx_ & 7;             \
            int tok_ = toks[r_];                                                  \
            const float* src_ = x + (size_t)(tok_ < 0 ? 0 : tok_) * DM            \
                                + k0_ + q_ * 4;                                   \
            cpa16(ab_ + (uint32_t)(r_ * SST + q_ * 4) * 4, src_,                  \
                  tok_ >= 0 ? 16 : 0);                                            \
        }                                                                         \
        uint32_t bb_ = ab_ + 128u * SST * 4u;                                     \
        _Pragma("unroll")                                                         \
        for (int i_ = 0; i_ < 4; i_++) {                                          \
            int idx_ = tid + i_ * 256, h_ = idx_ >> 9, rem_ = idx_ & 511;         \
            int r_ = rem_ >> 3, q_ = rem_ & 7;                                    \
            const float* src_ = W1e + (size_t)(h_ * FF + n0 + r_) * DM            \
                                + k0_ + q_ * 4;                                   \
            cpa16(bb_ + (uint32_t)((h_ * 64 + r_) * SST + q_ * 4) * 4, src_, 16); \
        }                                                                         \
        CP_COMMIT();                                                              \
    } while (0)

    ISSUE1(0, 0);
    ISSUE1(1, 1);

    for (int c = 0; c < NC; ++c) {
        int s = c & 1;
        if (c + 1 < NC) CP_WAIT1(); else CP_WAIT0();
        __syncthreads();
        const uint32_t* SA = dynw + s * STGW;
        const uint32_t* SB = SA + 128 * SST;
        #pragma unroll
        for (int kk = 0; kk < TKC; kk += 8) {
            uint32_t af[4][4];
            #pragma unroll
            for (int mt = 0; mt < 4; mt++) {
                int rb = wm + mt * 16;
                af[mt][0] = tfb(SA[(rb + g)     * SST + kk + tig]);
                af[mt][1] = tfb(SA[(rb + g + 8) * SST + kk + tig]);
                af[mt][2] = tfb(SA[(rb + g)     * SST + kk + tig + 4]);
                af[mt][3] = tfb(SA[(rb + g + 8) * SST + kk + tig + 4]);
            }
            uint32_t bf[2][2][2];
            #pragma unroll
            for (int h = 0; h < 2; h++)
                #pragma unroll
                for (int nt = 0; nt < 2; nt++) {
                    int rb = h * 64 + wn + nt * 8;
                    bf[h][nt][0] = tfb(SB[(rb + g) * SST + kk + tig]);
                    bf[h][nt][1] = tfb(SB[(rb + g) * SST + kk + tig + 4]);
                }
            #pragma unroll
            for (int h = 0; h < 2; h++)
                #pragma unroll
                for (int mt = 0; mt < 4; mt++)
                    #pragma unroll
                    for (int nt = 0; nt < 2; nt++)
                        mma8(acc[h][mt][nt], af[mt], bf[h][nt]);
        }
        __syncthreads();
        if (c + 2 < NC) ISSUE1(c + 2, s);
    }

    const float* b1e  = b1 + (size_t)e * 2 * FF;
    float*       acte = g_act + (size_t)e * MAXT * FF;
    #pragma unroll
    for (int mt = 0; mt < 4; mt++)
        #pragma unroll
        for (int rr = 0; rr < 2; rr++) {
            int mg = m0 + wm + mt * 16 + g + rr * 8;
            if (mg >= cnt) continue;
            float* orow = acte + (size_t)mg * FF;
            #pragma unroll
            for (int nt = 0; nt < 2; nt++) {
                int col = n0 + wn + nt * 8 + tig * 2;
                float h1a = acc[0][mt][nt][rr * 2 + 0] + b1e[col];
                float h1b = acc[0][mt][nt][rr * 2 + 1] + b1e[col + 1];
                float h2a = acc[1][mt][nt][rr * 2 + 0] + b1e[FF + col];
                float h2b = acc[1][mt][nt][rr * 2 + 1] + b1e[FF + col + 1];
                float2 o;
                o.x = h1a * h2a / (1.f + __expf(-h2a));
                o.y = h1b * h2b / (1.f + __expf(-h2b));
                *(float2*)(orow + col) = o;
            }
        }
    #undef ISSUE1
}

// ---------------------------------------------------------------------------
// GEMM2: tile 128(M) x 128(N); gated atomic scatter into out
__global__ __launch_bounds__(256, 2) void gemm2_k(const float* __restrict__ W2,
                                                  const float* __restrict__ b2,
                                                  float* __restrict__ out) {
    int e   = blockIdx.z;
    int cnt = g_cnt[e];
    int m0  = blockIdx.y * 128;
    if (m0 >= cnt) return;
    int n0  = blockIdx.x * 128;

    extern __shared__ uint32_t dynw[];
    uint32_t sb = smem_u32(dynw);
    __shared__ int   toks[128];
    __shared__ float wts[128];

    int tid = threadIdx.x, wid = tid >> 5, lane = tid & 31;
    int g = lane >> 2, tig = lane & 3;
    int wm = (wid & 1) * 64, wn = (wid >> 1) * 32;

    if (tid < 128) {
        int m = m0 + tid;
        toks[tid] = (m < cnt) ? g_tok[e * MAXT + m] : -1;
        wts[tid]  = (m < cnt) ? g_wt[e * MAXT + m] : 0.f;
    }
    __syncthreads();

    const float* W2e  = W2 + (size_t)e * DM * FF;
    const float* acte = g_act + (size_t)e * MAXT * FF;

    float acc[4][4][4];
    #pragma unroll
    for (int mt = 0; mt < 4; mt++)
        #pragma unroll
        for (int nt = 0; nt < 4; nt++)
            #pragma unroll
            for (int j = 0; j < 4; j++) acc[mt][nt][j] = 0.f;

    const int NC = FF / TKC;    // 64 chunks

    #define ISSUE2(c, s) do {                                                     \
        int k0_ = (c) * TKC;                                                      \
        uint32_t ab_ = sb + (uint32_t)(s) * STGB;                                 \
        _Pragma("unroll")                                                         \
        for (int i_ = 0; i_ < 4; i_++) {                                          \
            int idx_ = tid + i_ * 256, r_ = idx_ >> 3, q_ = idx_ & 7;             \
            int ok_ = (m0 + r_ < cnt);                                            \
            const float* src_ = acte + (size_t)(m0 + (ok_ ? r_ : 0)) * FF         \
                                + k0_ + q_ * 4;                                   \
            cpa16(ab_ + (uint32_t)(r_ * SST + q_ * 4) * 4, src_, ok_ ? 16 : 0);   \
        }                                                                         \
        uint32_t bb_ = ab_ + 128u * SST * 4u;                                     \
        _Pragma("unroll")                                                         \
        for (int i_ = 0; i_ < 4; i_++) {                                          \
            int idx_ = tid + i_ * 256, r_ = idx_ >> 3, q_ = idx_ & 7;             \
            const float* src_ = W2e + (size_t)(n0 + r_) * FF + k0_ + q_ * 4;      \
            cpa16(bb_ + (uint32_t)(r_ * SST + q_ * 4) * 4, src_, 16);             \
        }                                                                         \
        CP_COMMIT();                                                              \
    } while (0)

    ISSUE2(0, 0);
    ISSUE2(1, 1);

    for (int c = 0; c < NC; ++c) {
        int s = c & 1;
        if (c + 1 < NC) CP_WAIT1(); else CP_WAIT0();
        __syncthreads();
        const uint32_t* SA = dynw + s * STGW;
        const uint32_t* SB = SA + 128 * SST;
        #pragma unroll
        for (int kk = 0; kk < TKC; kk += 8) {
            uint32_t af[4][4];
            #pragma unroll
            for (int mt = 0; mt < 4; mt++) {
                int rb = wm + mt * 16;
                af[mt][0] = tfb(SA[(rb + g)     * SST + kk + tig]);
                af[mt][1] = tfb(SA[(rb + g + 8) * SST + kk + tig]);
                af[mt][2] = tfb(SA[(rb + g)     * SST + kk + tig + 4]);
                af[mt][3] = tfb(SA[(rb + g + 8) * SST + kk + tig + 4]);
            }
            uint32_t bf[4][2];
            #pragma unroll
            for (int nt = 0; nt < 4; nt++) {
                int rb = wn + nt * 8;
                bf[nt][0] = tfb(SB[(rb + g) * SST + kk + tig]);
                bf[nt][1] = tfb(SB[(rb + g) * SST + kk + tig + 4]);
            }
            #pragma unroll
            for (int mt = 0; mt < 4; mt++)
                #pragma unroll
                for (int nt = 0; nt < 4; nt++)
                    mma8(acc[mt][nt], af[mt], bf[nt]);
        }
        __syncthreads();
        if (c + 2 < NC) ISSUE2(c + 2, s);
    }

    const float* b2e = b2 + (size_t)e * DM;
    #pragma unroll
    for (int mt = 0; mt < 4; mt++)
        #pragma unroll
        for (int rr = 0; rr < 2; rr++) {
            int lm = wm + mt * 16 + g + rr * 8;
            int mg = m0 + lm;
            if (mg >= cnt) continue;
            int   tok = toks[lm];
            float w   = wts[lm];
            float* dst = out + (size_t)tok * DM;
            #pragma unroll
            for (int nt = 0; nt < 4; nt++) {
                int col = n0 + wn + nt * 8 + tig * 2;
                atomicAdd(dst + col,     w * (acc[mt][nt][rr * 2 + 0] + b2e[col]));
                atomicAdd(dst + col + 1, w * (acc[mt][nt][rr * 2 + 1] + b2e[col + 1]));
            }
        }
    #undef ISSUE2
}

// ---------------------------------------------------------------------------
extern "C" void kernel_launch(void* const* d_in, const int* in_sizes, int n_in,
                              void* d_out, int out_size) {
    const float* x    = (const float*)d_in[0];
    const float* Wr   = (const float*)d_in[1];
    const float* temp = (const float*)d_in[2];
    const float* W1   = (const float*)d_in[3];
    const float* b1   = (const float*)d_in[4];
    const float* W2   = (const float*)d_in[5];
    const float* b2   = (const float*)d_in[6];
    float* out = (float*)d_out;

    int T  = in_sizes[0] / DM;
    int MB = (T + 127) / 128;

    const int DSM = 2 * STGB;
    cudaFuncSetAttribute(gemm1_k, cudaFuncAttributeMaxDynamicSharedMemorySize, DSM);
    cudaFuncSetAttribute(gemm2_k, cudaFuncAttributeMaxDynamicSharedMemorySize, DSM);

    cudaMemsetAsync(d_out, 0, (size_t)out_size * sizeof(float), 0);
    init_k<<<1, 32>>>();
    router_k<<<T, 256>>>(x, Wr, temp);

    dim3 g1(FF / 64, MB, NE);
    gemm1_k<<<g1, 256, DSM>>>(x, W1, b1);

    dim3 g2(DM / 128, MB, NE);
    gemm2_k<<<g2, 256, DSM>>>(W2, b2, out);
}

// round 6
// speedup vs baseline: 4.0899x; 1.0456x over previous
#include <cuda_runtime.h>
#include <cstdint>

#define DM   1024
#define NE   8
#define FF   2048
#define MAXT 4096
#define TKC  32
#define NSTG 3
#define STGW (256 * 32)      // words per stage: 256 rows x 32 words
#define STGB (STGW * 4)      // 32768 bytes

// -------- persistent device scratch (no dynamic alloc allowed) -------------
__device__ int   g_cnt[NE];
__device__ int   g_tok[NE * MAXT];
__device__ float g_wt [NE * MAXT];
__device__ float g_act[(size_t)NE * MAXT * FF];

// ---------------------------------------------------------------------------
__device__ __forceinline__ uint32_t f2tf(float f) {
    uint32_t r; asm("cvt.rna.tf32.f32 %0, %1;" : "=r"(r) : "f"(f)); return r;
}
__device__ __forceinline__ uint32_t tfb(uint32_t raw) {
    return f2tf(__uint_as_float(raw));
}
__device__ __forceinline__ uint32_t smem_u32(const void* p) {
    uint32_t a;
    asm("{ .reg .u64 t; cvta.to.shared.u64 t, %1; cvt.u32.u64 %0, t; }" : "=r"(a) : "l"(p));
    return a;
}
__device__ __forceinline__ void cpa16(uint32_t dst, const void* src, int sz) {
    asm volatile("cp.async.cg.shared.global [%0], [%1], 16, %2;"
                 :: "r"(dst), "l"(src), "r"(sz) : "memory");
}
#define CP_COMMIT() asm volatile("cp.async.commit_group;" ::: "memory")
#define CP_WAIT2()  asm volatile("cp.async.wait_group 2;" ::: "memory")
#define CP_WAIT0()  asm volatile("cp.async.wait_group 0;" ::: "memory")

// swizzled word offset within a stage: 32-word rows, quad ^= (row & 7)
__device__ __forceinline__ uint32_t swo(int row, int q) {
    return (uint32_t)(row * 32 + ((q ^ (row & 7)) << 2));
}

__device__ __forceinline__ void mma8(float c[4], const uint32_t a[4], const uint32_t b[2]) {
    asm volatile(
        "mma.sync.aligned.m16n8k8.row.col.f32.tf32.tf32.f32 "
        "{%0,%1,%2,%3}, {%4,%5,%6,%7}, {%8,%9}, {%0,%1,%2,%3};"
        : "+f"(c[0]), "+f"(c[1]), "+f"(c[2]), "+f"(c[3])
        : "r"(a[0]), "r"(a[1]), "r"(a[2]), "r"(a[3]), "r"(b[0]), "r"(b[1]));
}

// ---------------------------------------------------------------------------
__global__ void init_k() { if (threadIdx.x < NE) g_cnt[threadIdx.x] = 0; }

__global__ void router_k(const float* __restrict__ x,
                         const float* __restrict__ Wr,
                         const float* __restrict__ temp) {
    __shared__ float xs[DM];
    __shared__ float lg[NE];
    int t = blockIdx.x;
    const float* xr = x + (size_t)t * DM;
    for (int i = threadIdx.x; i < DM; i += blockDim.x) xs[i] = xr[i];
    __syncthreads();
    int w = threadIdx.x >> 5, lane = threadIdx.x & 31;
    if (w < NE) {
        const float* wr = Wr + (size_t)w * DM;
        float s = 0.f;
        for (int i = lane; i < DM; i += 32) s += xs[i] * wr[i];
        #pragma unroll
        for (int o = 16; o; o >>= 1) s += __shfl_xor_sync(0xffffffffu, s, o);
        if (lane == 0) lg[w] = s;
    }
    __syncthreads();
    if (threadIdx.x == 0) {
        float it = 1.f / temp[0];
        float l[NE];
        #pragma unroll
        for (int e = 0; e < NE; e++) l[e] = lg[e] * it;
        int i0 = 0;
        #pragma unroll
        for (int e = 1; e < NE; e++) if (l[e] > l[i0]) i0 = e;
        int i1 = (i0 == 0) ? 1 : 0;
        #pragma unroll
        for (int e = 0; e < NE; e++) if (e != i0 && l[e] > l[i1]) i1 = e;
        float m  = l[i0];
        float e0 = __expf(l[i0] - m), e1 = __expf(l[i1] - m);
        float inv = 1.f / (e0 + e1);
        int s0 = atomicAdd(&g_cnt[i0], 1);
        g_tok[i0 * MAXT + s0] = t;  g_wt[i0 * MAXT + s0] = e0 * inv;
        int s1 = atomicAdd(&g_cnt[i1], 1);
        g_tok[i1 * MAXT + s1] = t;  g_wt[i1 * MAXT + s1] = e1 * inv;
    }
}

// ---------------------------------------------------------------------------
// GEMM1: CTA 128(M) x 64(N) over BOTH W1 halves (B tile = 128 rows).
// 4 warps: wm in {0,64}, wn in {0,32}; warp computes 64x32 of h1 AND h2.
__global__ __launch_bounds__(128, 2) void gemm1_k(const float* __restrict__ x,
                                                  const float* __restrict__ W1,
                                                  const float* __restrict__ b1) {
    int e   = blockIdx.z;
    int cnt = g_cnt[e];
    int m0  = blockIdx.y * 128;
    if (m0 >= cnt) return;
    int n0  = blockIdx.x * 64;

    extern __shared__ uint32_t dynw[];
    uint32_t sb = smem_u32(dynw);
    __shared__ int toks[128];

    int tid = threadIdx.x, wid = tid >> 5, lane = tid & 31;
    int g = lane >> 2, tig = lane & 3;
    int wm = (wid & 1) * 64, wn = (wid >> 1) * 32;

    if (tid < 128) { int m = m0 + tid; toks[tid] = (m < cnt) ? g_tok[e * MAXT + m] : -1; }
    __syncthreads();

    const float* W1e = W1 + (size_t)e * (2 * FF) * DM;

    float acc[2][4][4][4];
    #pragma unroll
    for (int h = 0; h < 2; h++)
        #pragma unroll
        for (int mt = 0; mt < 4; mt++)
            #pragma unroll
            for (int nt = 0; nt < 4; nt++)
                #pragma unroll
                for (int j = 0; j < 4; j++) acc[h][mt][nt][j] = 0.f;

    const int NC = DM / TKC;    // 32

    #define ISSUE1(c, s) do {                                                   \
        int k0_ = (c) * TKC;                                                    \
        uint32_t st_ = sb + (uint32_t)(s) * STGB;                               \
        _Pragma("unroll")                                                       \
        for (int i_ = 0; i_ < 16; i_++) {                                       \
            int idx_ = tid + i_ * 128, row_ = idx_ >> 3, q_ = idx_ & 7;         \
            uint32_t dst_ = st_ + swo(row_, q_) * 4;                            \
            if (row_ < 128) {                                                   \
                int tok_ = toks[row_];                                          \
                const float* src_ = x + (size_t)(tok_ < 0 ? 0 : tok_) * DM      \
                                    + k0_ + q_ * 4;                             \
                cpa16(dst_, src_, tok_ >= 0 ? 16 : 0);                          \
            } else {                                                            \
                int j_ = row_ - 128, h_ = j_ >> 6, jr_ = j_ & 63;               \
                const float* src_ = W1e + (size_t)(h_ * FF + n0 + jr_) * DM     \
                                    + k0_ + q_ * 4;                             \
                cpa16(dst_, src_, 16);                                          \
            }                                                                   \
        }                                                                       \
        CP_COMMIT();                                                            \
    } while (0)

    ISSUE1(0, 0); ISSUE1(1, 1); ISSUE1(2, 2);

    for (int c = 0; c < NC; ++c) {
        int s = c % NSTG;
        if (c + 1 < NC) CP_WAIT2(); else CP_WAIT0();
        __syncthreads();
        const uint32_t* ST = dynw + s * STGW;
        #pragma unroll
        for (int kk = 0; kk < TKC; kk += 8) {
            int q0 = kk >> 2, q1 = q0 + 1;
            uint32_t af[4][4];
            #pragma unroll
            for (int mt = 0; mt < 4; mt++) {
                int rb = wm + mt * 16;
                af[mt][0] = tfb(ST[swo(rb + g,     q0) + tig]);
                af[mt][1] = tfb(ST[swo(rb + g + 8, q0) + tig]);
                af[mt][2] = tfb(ST[swo(rb + g,     q1) + tig]);
                af[mt][3] = tfb(ST[swo(rb + g + 8, q1) + tig]);
            }
            uint32_t bf[2][4][2];
            #pragma unroll
            for (int h = 0; h < 2; h++)
                #pragma unroll
                for (int nt = 0; nt < 4; nt++) {
                    int rb = 128 + h * 64 + wn + nt * 8 + g;
                    bf[h][nt][0] = tfb(ST[swo(rb, q0) + tig]);
                    bf[h][nt][1] = tfb(ST[swo(rb, q1) + tig]);
                }
            #pragma unroll
            for (int h = 0; h < 2; h++)
                #pragma unroll
                for (int mt = 0; mt < 4; mt++)
                    #pragma unroll
                    for (int nt = 0; nt < 4; nt++)
                        mma8(acc[h][mt][nt], af[mt], bf[h][nt]);
        }
        __syncthreads();
        if (c + NSTG < NC) ISSUE1(c + NSTG, s);
    }

    const float* b1e  = b1 + (size_t)e * 2 * FF;
    float*       acte = g_act + (size_t)e * MAXT * FF;
    #pragma unroll
    for (int mt = 0; mt < 4; mt++)
        #pragma unroll
        for (int rr = 0; rr < 2; rr++) {
            int mg = m0 + wm + mt * 16 + g + rr * 8;
            if (mg >= cnt) continue;
            float* orow = acte + (size_t)mg * FF;
            #pragma unroll
            for (int nt = 0; nt < 4; nt++) {
                int col = n0 + wn + nt * 8 + tig * 2;
                float h1a = acc[0][mt][nt][rr * 2 + 0] + b1e[col];
                float h1b = acc[0][mt][nt][rr * 2 + 1] + b1e[col + 1];
                float h2a = acc[1][mt][nt][rr * 2 + 0] + b1e[FF + col];
                float h2b = acc[1][mt][nt][rr * 2 + 1] + b1e[FF + col + 1];
                float2 o;
                o.x = h1a * h2a / (1.f + __expf(-h2a));
                o.y = h1b * h2b / (1.f + __expf(-h2b));
                *(float2*)(orow + col) = o;
            }
        }
    #undef ISSUE1
}

// ---------------------------------------------------------------------------
// GEMM2: CTA 128(M) x 128(N); 4 warps 2x2; warp tile 64x64; atomic scatter.
__global__ __launch_bounds__(128, 2) void gemm2_k(const float* __restrict__ W2,
                                                  const float* __restrict__ b2,
                                                  float* __restrict__ out) {
    int e   = blockIdx.z;
    int cnt = g_cnt[e];
    int m0  = blockIdx.y * 128;
    if (m0 >= cnt) return;
    int n0  = blockIdx.x * 128;

    extern __shared__ uint32_t dynw[];
    uint32_t sb = smem_u32(dynw);
    __shared__ int   toks[128];
    __shared__ float wts[128];

    int tid = threadIdx.x, wid = tid >> 5, lane = tid & 31;
    int g = lane >> 2, tig = lane & 3;
    int wm = (wid & 1) * 64, wn = (wid >> 1) * 64;

    if (tid < 128) {
        int m = m0 + tid;
        toks[tid] = (m < cnt) ? g_tok[e * MAXT + m] : -1;
        wts[tid]  = (m < cnt) ? g_wt[e * MAXT + m] : 0.f;
    }
    __syncthreads();

    const float* W2e  = W2 + (size_t)e * DM * FF;
    const float* acte = g_act + (size_t)e * MAXT * FF;

    float acc[4][8][4];
    #pragma unroll
    for (int mt = 0; mt < 4; mt++)
        #pragma unroll
        for (int nt = 0; nt < 8; nt++)
            #pragma unroll
            for (int j = 0; j < 4; j++) acc[mt][nt][j] = 0.f;

    const int NC = FF / TKC;    // 64

    #define ISSUE2(c, s) do {                                                   \
        int k0_ = (c) * TKC;                                                    \
        uint32_t st_ = sb + (uint32_t)(s) * STGB;                               \
        _Pragma("unroll")                                                       \
        for (int i_ = 0; i_ < 16; i_++) {                                       \
            int idx_ = tid + i_ * 128, row_ = idx_ >> 3, q_ = idx_ & 7;         \
            uint32_t dst_ = st_ + swo(row_, q_) * 4;                            \
            if (row_ < 128) {                                                   \
                int ok_ = (m0 + row_ < cnt);                                    \
                const float* src_ = acte + (size_t)(m0 + (ok_ ? row_ : 0)) * FF \
                                    + k0_ + q_ * 4;                             \
                cpa16(dst_, src_, ok_ ? 16 : 0);                                \
            } else {                                                            \
                int j_ = row_ - 128;                                            \
                const float* src_ = W2e + (size_t)(n0 + j_) * FF + k0_ + q_ * 4;\
                cpa16(dst_, src_, 16);                                          \
            }                                                                   \
        }                                                                       \
        CP_COMMIT();                                                            \
    } while (0)

    ISSUE2(0, 0); ISSUE2(1, 1); ISSUE2(2, 2);

    for (int c = 0; c < NC; ++c) {
        int s = c % NSTG;
        if (c + 1 < NC) CP_WAIT2(); else CP_WAIT0();
        __syncthreads();
        const uint32_t* ST = dynw + s * STGW;
        #pragma unroll
        for (int kk = 0; kk < TKC; kk += 8) {
            int q0 = kk >> 2, q1 = q0 + 1;
            uint32_t af[4][4];
            #pragma unroll
            for (int mt = 0; mt < 4; mt++) {
                int rb = wm + mt * 16;
                af[mt][0] = tfb(ST[swo(rb + g,     q0) + tig]);
                af[mt][1] = tfb(ST[swo(rb + g + 8, q0) + tig]);
                af[mt][2] = tfb(ST[swo(rb + g,     q1) + tig]);
                af[mt][3] = tfb(ST[swo(rb + g + 8, q1) + tig]);
            }
            uint32_t bf[8][2];
            #pragma unroll
            for (int nt = 0; nt < 8; nt++) {
                int rb = 128 + wn + nt * 8 + g;
                bf[nt][0] = tfb(ST[swo(rb, q0) + tig]);
                bf[nt][1] = tfb(ST[swo(rb, q1) + tig]);
            }
            #pragma unroll
            for (int mt = 0; mt < 4; mt++)
                #pragma unroll
                for (int nt = 0; nt < 8; nt++)
                    mma8(acc[mt][nt], af[mt], bf[nt]);
        }
        __syncthreads();
        if (c + NSTG < NC) ISSUE2(c + NSTG, s);
    }

    const float* b2e = b2 + (size_t)e * DM;
    #pragma unroll
    for (int mt = 0; mt < 4; mt++)
        #pragma unroll
        for (int rr = 0; rr < 2; rr++) {
            int lm = wm + mt * 16 + g + rr * 8;
            int mg = m0 + lm;
            if (mg >= cnt) continue;
            int   tok = toks[lm];
            float w   = wts[lm];
            float* dst = out + (size_t)tok * DM;
            #pragma unroll
            for (int nt = 0; nt < 8; nt++) {
                int col = n0 + wn + nt * 8 + tig * 2;
                atomicAdd(dst + col,     w * (acc[mt][nt][rr * 2 + 0] + b2e[col]));
                atomicAdd(dst + col + 1, w * (acc[mt][nt][rr * 2 + 1] + b2e[col + 1]));
            }
        }
    #undef ISSUE2
}

// ---------------------------------------------------------------------------
extern "C" void kernel_launch(void* const* d_in, const int* in_sizes, int n_in,
                              void* d_out, int out_size) {
    const float* x    = (const float*)d_in[0];
    const float* Wr   = (const float*)d_in[1];
    const float* temp = (const float*)d_in[2];
    const float* W1   = (const float*)d_in[3];
    const float* b1   = (const float*)d_in[4];
    const float* W2   = (const float*)d_in[5];
    const float* b2   = (const float*)d_in[6];
    float* out = (float*)d_out;

    int T  = in_sizes[0] / DM;
    int MB = (T + 127) / 128;

    const int DSM = NSTG * STGB;   // 98304
    cudaFuncSetAttribute(gemm1_k, cudaFuncAttributeMaxDynamicSharedMemorySize, DSM);
    cudaFuncSetAttribute(gemm2_k, cudaFuncAttributeMaxDynamicSharedMemorySize, DSM);

    cudaMemsetAsync(d_out, 0, (size_t)out_size * sizeof(float), 0);
    init_k<<<1, 32>>>();
    router_k<<<T, 256>>>(x, Wr, temp);

    dim3 g1(FF / 64, MB, NE);
    gemm1_k<<<g1, 128, DSM>>>(x, W1, b1);

    dim3 g2(DM / 128, MB, NE);
    gemm2_k<<<g2, 128, DSM>>>(W2, b2, out);
}

// round 7
// speedup vs baseline: 4.1348x; 1.0110x over previous
#include <cuda_runtime.h>
#include <cstdint>

#define DM   1024
#define NE   8
#define FF   2048
#define MAXT 4096
#define TKC  32
#define NSTG 3
#define STGW (256 * 32)      // words per stage: 256 rows x 32 words
#define STGB (STGW * 4)      // 32768 bytes

// -------- persistent device scratch (no dynamic alloc allowed) -------------
__device__ int   g_cnt[NE];
__device__ int   g_tok[NE * MAXT];
__device__ float g_wt [NE * MAXT];
__device__ float g_act[(size_t)NE * MAXT * FF];

// ---------------------------------------------------------------------------
__device__ __forceinline__ uint32_t f2tf(float f) {
    uint32_t r; asm("cvt.rna.tf32.f32 %0, %1;" : "=r"(r) : "f"(f)); return r;
}
__device__ __forceinline__ uint32_t tfb(uint32_t raw) {
    return f2tf(__uint_as_float(raw));
}
__device__ __forceinline__ uint32_t smem_u32(const void* p) {
    uint32_t a;
    asm("{ .reg .u64 t; cvta.to.shared.u64 t, %1; cvt.u32.u64 %0, t; }" : "=r"(a) : "l"(p));
    return a;
}
__device__ __forceinline__ void cpa16(uint32_t dst, const void* src, int sz) {
    asm volatile("cp.async.cg.shared.global [%0], [%1], 16, %2;"
                 :: "r"(dst), "l"(src), "r"(sz) : "memory");
}
#define CP_COMMIT() asm volatile("cp.async.commit_group;" ::: "memory")
#define CP_WAIT1()  asm volatile("cp.async.wait_group 1;" ::: "memory")
#define CP_WAIT0()  asm volatile("cp.async.wait_group 0;" ::: "memory")

// swizzled word offset within a stage: 32-word rows, quad ^= (row & 7)
__device__ __forceinline__ uint32_t swo(int row, int q) {
    return (uint32_t)(row * 32 + ((q ^ (row & 7)) << 2));
}

__device__ __forceinline__ void mma8(float c[4], const uint32_t a[4], const uint32_t b[2]) {
    asm volatile(
        "mma.sync.aligned.m16n8k8.row.col.f32.tf32.tf32.f32 "
        "{%0,%1,%2,%3}, {%4,%5,%6,%7}, {%8,%9}, {%0,%1,%2,%3};"
        : "+f"(c[0]), "+f"(c[1]), "+f"(c[2]), "+f"(c[3])
        : "r"(a[0]), "r"(a[1]), "r"(a[2]), "r"(a[3]), "r"(b[0]), "r"(b[1]));
}

// ---------------------------------------------------------------------------
__global__ void init_k() { if (threadIdx.x < NE) g_cnt[threadIdx.x] = 0; }

__global__ void router_k(const float* __restrict__ x,
                         const float* __restrict__ Wr,
                         const float* __restrict__ temp) {
    __shared__ float xs[DM];
    __shared__ float lg[NE];
    int t = blockIdx.x;
    const float* xr = x + (size_t)t * DM;
    for (int i = threadIdx.x; i < DM; i += blockDim.x) xs[i] = xr[i];
    __syncthreads();
    int w = threadIdx.x >> 5, lane = threadIdx.x & 31;
    if (w < NE) {
        const float* wr = Wr + (size_t)w * DM;
        float s = 0.f;
        for (int i = lane; i < DM; i += 32) s += xs[i] * wr[i];
        #pragma unroll
        for (int o = 16; o; o >>= 1) s += __shfl_xor_sync(0xffffffffu, s, o);
        if (lane == 0) lg[w] = s;
    }
    __syncthreads();
    if (threadIdx.x == 0) {
        float it = 1.f / temp[0];
        float l[NE];
        #pragma unroll
        for (int e = 0; e < NE; e++) l[e] = lg[e] * it;
        int i0 = 0;
        #pragma unroll
        for (int e = 1; e < NE; e++) if (l[e] > l[i0]) i0 = e;
        int i1 = (i0 == 0) ? 1 : 0;
        #pragma unroll
        for (int e = 0; e < NE; e++) if (e != i0 && l[e] > l[i1]) i1 = e;
        float m  = l[i0];
        float e0 = __expf(l[i0] - m), e1 = __expf(l[i1] - m);
        float inv = 1.f / (e0 + e1);
        int s0 = atomicAdd(&g_cnt[i0], 1);
        g_tok[i0 * MAXT + s0] = t;  g_wt[i0 * MAXT + s0] = e0 * inv;
        int s1 = atomicAdd(&g_cnt[i1], 1);
        g_tok[i1 * MAXT + s1] = t;  g_wt[i1 * MAXT + s1] = e1 * inv;
    }
}

// ---------------------------------------------------------------------------
// GEMM1: CTA 128(M) x 64(N) over BOTH W1 halves (B tile = 128 rows).
// 4 warps: wm in {0,64}, wn in {0,32}; warp computes 64x32 of h1 AND h2.
__global__ __launch_bounds__(128, 2) void gemm1_k(const float* __restrict__ x,
                                                  const float* __restrict__ W1,
                                                  const float* __restrict__ b1) {
    int e   = blockIdx.z;
    int cnt = g_cnt[e];
    int m0  = blockIdx.y * 128;
    if (m0 >= cnt) return;
    int n0  = blockIdx.x * 64;

    extern __shared__ uint32_t dynw[];
    uint32_t sb = smem_u32(dynw);
    __shared__ int toks[128];

    int tid = threadIdx.x, wid = tid >> 5, lane = tid & 31;
    int g = lane >> 2, tig = lane & 3;
    int wm = (wid & 1) * 64, wn = (wid >> 1) * 32;

    if (tid < 128) { int m = m0 + tid; toks[tid] = (m < cnt) ? g_tok[e * MAXT + m] : -1; }
    __syncthreads();

    const float* W1e = W1 + (size_t)e * (2 * FF) * DM;

    float acc[2][4][4][4];
    #pragma unroll
    for (int h = 0; h < 2; h++)
        #pragma unroll
        for (int mt = 0; mt < 4; mt++)
            #pragma unroll
            for (int nt = 0; nt < 4; nt++)
                #pragma unroll
                for (int j = 0; j < 4; j++) acc[h][mt][nt][j] = 0.f;

    const int NC = DM / TKC;    // 32

    #define ISSUE1(c, s) do {                                                   \
        int k0_ = (c) * TKC;                                                    \
        uint32_t st_ = sb + (uint32_t)(s) * STGB;                               \
        _Pragma("unroll")                                                       \
        for (int i_ = 0; i_ < 16; i_++) {                                       \
            int idx_ = tid + i_ * 128, row_ = idx_ >> 3, q_ = idx_ & 7;         \
            uint32_t dst_ = st_ + swo(row_, q_) * 4;                            \
            if (row_ < 128) {                                                   \
                int tok_ = toks[row_];                                          \
                const float* src_ = x + (size_t)(tok_ < 0 ? 0 : tok_) * DM      \
                                    + k0_ + q_ * 4;                             \
                cpa16(dst_, src_, tok_ >= 0 ? 16 : 0);                          \
            } else {                                                            \
                int j_ = row_ - 128, h_ = j_ >> 6, jr_ = j_ & 63;               \
                const float* src_ = W1e + (size_t)(h_ * FF + n0 + jr_) * DM     \
                                    + k0_ + q_ * 4;                             \
                cpa16(dst_, src_, 16);                                          \
            }                                                                   \
        }                                                                       \
        CP_COMMIT();                                                            \
    } while (0)

    #define LDFRAG1(buf, ST, kk) do {                                           \
        int q0_ = (kk) >> 2, q1_ = q0_ + 1;                                     \
        _Pragma("unroll")                                                       \
        for (int mt = 0; mt < 4; mt++) {                                        \
            int rb = wm + mt * 16;                                              \
            af[buf][mt][0] = tfb(ST[swo(rb + g,     q0_) + tig]);               \
            af[buf][mt][1] = tfb(ST[swo(rb + g + 8, q0_) + tig]);               \
            af[buf][mt][2] = tfb(ST[swo(rb + g,     q1_) + tig]);               \
            af[buf][mt][3] = tfb(ST[swo(rb + g + 8, q1_) + tig]);               \
        }                                                                       \
        _Pragma("unroll")                                                       \
        for (int h = 0; h < 2; h++)                                             \
            _Pragma("unroll")                                                   \
            for (int nt = 0; nt < 4; nt++) {                                    \
                int rb = 128 + h * 64 + wn + nt * 8 + g;                        \
                bf[buf][h][nt][0] = tfb(ST[swo(rb, q0_) + tig]);                \
                bf[buf][h][nt][1] = tfb(ST[swo(rb, q1_) + tig]);                \
            }                                                                   \
    } while (0)

    ISSUE1(0, 0); ISSUE1(1, 1);

    uint32_t af[2][4][4];
    uint32_t bf[2][2][4][2];

    for (int c = 0; c < NC; ++c) {
        if (c + 1 < NC) CP_WAIT1(); else CP_WAIT0();
        __syncthreads();
        if (c + 2 < NC) ISSUE1(c + 2, (c + 2) % NSTG);
        const uint32_t* ST = dynw + (c % NSTG) * STGW;
        LDFRAG1(0, ST, 0);
        #pragma unroll
        for (int kk = 0; kk < TKC; kk += 8) {
            int cur = (kk >> 3) & 1;
            if (kk + 8 < TKC) LDFRAG1(cur ^ 1, ST, kk + 8);
            #pragma unroll
            for (int h = 0; h < 2; h++)
                #pragma unroll
                for (int mt = 0; mt < 4; mt++)
                    #pragma unroll
                    for (int nt = 0; nt < 4; nt++)
                        mma8(acc[h][mt][nt], af[cur][mt], bf[cur][h][nt]);
        }
    }

    const float* b1e  = b1 + (size_t)e * 2 * FF;
    float*       acte = g_act + (size_t)e * MAXT * FF;
    #pragma unroll
    for (int mt = 0; mt < 4; mt++)
        #pragma unroll
        for (int rr = 0; rr < 2; rr++) {
            int mg = m0 + wm + mt * 16 + g + rr * 8;
            if (mg >= cnt) continue;
            float* orow = acte + (size_t)mg * FF;
            #pragma unroll
            for (int nt = 0; nt < 4; nt++) {
                int col = n0 + wn + nt * 8 + tig * 2;
                float h1a = acc[0][mt][nt][rr * 2 + 0] + b1e[col];
                float h1b = acc[0][mt][nt][rr * 2 + 1] + b1e[col + 1];
                float h2a = acc[1][mt][nt][rr * 2 + 0] + b1e[FF + col];
                float h2b = acc[1][mt][nt][rr * 2 + 1] + b1e[FF + col + 1];
                float2 o;
                o.x = h1a * h2a / (1.f + __expf(-h2a));
                o.y = h1b * h2b / (1.f + __expf(-h2b));
                *(float2*)(orow + col) = o;
            }
        }
    #undef ISSUE1
    #undef LDFRAG1
}

// ---------------------------------------------------------------------------
// GEMM2: CTA 128(M) x 128(N); 4 warps 2x2; warp tile 64x64; atomic scatter.
__global__ __launch_bounds__(128, 2) void gemm2_k(const float* __restrict__ W2,
                                                  const float* __restrict__ b2,
                                                  float* __restrict__ out) {
    int e   = blockIdx.z;
    int cnt = g_cnt[e];
    int m0  = blockIdx.y * 128;
    if (m0 >= cnt) return;
    int n0  = blockIdx.x * 128;

    extern __shared__ uint32_t dynw[];
    uint32_t sb = smem_u32(dynw);
    __shared__ int   toks[128];
    __shared__ float wts[128];

    int tid = threadIdx.x, wid = tid >> 5, lane = tid & 31;
    int g = lane >> 2, tig = lane & 3;
    int wm = (wid & 1) * 64, wn = (wid >> 1) * 64;

    if (tid < 128) {
        int m = m0 + tid;
        toks[tid] = (m < cnt) ? g_tok[e * MAXT + m] : -1;
        wts[tid]  = (m < cnt) ? g_wt[e * MAXT + m] : 0.f;
    }
    __syncthreads();

    const float* W2e  = W2 + (size_t)e * DM * FF;
    const float* acte = g_act + (size_t)e * MAXT * FF;

    float acc[4][8][4];
    #pragma unroll
    for (int mt = 0; mt < 4; mt++)
        #pragma unroll
        for (int nt = 0; nt < 8; nt++)
            #pragma unroll
            for (int j = 0; j < 4; j++) acc[mt][nt][j] = 0.f;

    const int NC = FF / TKC;    // 64

    #define ISSUE2(c, s) do {                                                   \
        int k0_ = (c) * TKC;                                                    \
        uint32_t st_ = sb + (uint32_t)(s) * STGB;                               \
        _Pragma("unroll")                                                       \
        for (int i_ = 0; i_ < 16; i_++) {                                       \
            int idx_ = tid + i_ * 128, row_ = idx_ >> 3, q_ = idx_ & 7;         \
            uint32_t dst_ = st_ + swo(row_, q_) * 4;                            \
            if (row_ < 128) {                                                   \
                int ok_ = (m0 + row_ < cnt);                                    \
                const float* src_ = acte + (size_t)(m0 + (ok_ ? row_ : 0)) * FF \
                                    + k0_ + q_ * 4;                             \
                cpa16(dst_, src_, ok_ ? 16 : 0);                                \
            } else {                                                            \
                int j_ = row_ - 128;                                            \
                const float* src_ = W2e + (size_t)(n0 + j_) * FF + k0_ + q_ * 4;\
                cpa16(dst_, src_, 16);                                          \
            }                                                                   \
        }                                                                       \
        CP_COMMIT();                                                            \
    } while (0)

    #define LDFRAG2(buf, ST, kk) do {                                           \
        int q0_ = (kk) >> 2, q1_ = q0_ + 1;                                     \
        _Pragma("unroll")                                                       \
        for (int mt = 0; mt < 4; mt++) {                                        \
            int rb = wm + mt * 16;                                              \
            af[buf][mt][0] = tfb(ST[swo(rb + g,     q0_) + tig]);               \
            af[buf][mt][1] = tfb(ST[swo(rb + g + 8, q0_) + tig]);               \
            af[buf][mt][2] = tfb(ST[swo(rb + g,     q1_) + tig]);               \
            af[buf][mt][3] = tfb(ST[swo(rb + g + 8, q1_) + tig]);               \
        }                                                                       \
        _Pragma("unroll")                                                       \
        for (int nt = 0; nt < 8; nt++) {                                        \
            int rb = 128 + wn + nt * 8 + g;                                     \
            bf[buf][nt][0] = tfb(ST[swo(rb, q0_) + tig]);                       \
            bf[buf][nt][1] = tfb(ST[swo(rb, q1_) + tig]);                       \
        }                                                                       \
    } while (0)

    ISSUE2(0, 0); ISSUE2(1, 1);

    uint32_t af[2][4][4];
    uint32_t bf[2][8][2];

    for (int c = 0; c < NC; ++c) {
        if (c + 1 < NC) CP_WAIT1(); else CP_WAIT0();
        __syncthreads();
        if (c + 2 < NC) ISSUE2(c + 2, (c + 2) % NSTG);
        const uint32_t* ST = dynw + (c % NSTG) * STGW;
        LDFRAG2(0, ST, 0);
        #pragma unroll
        for (int kk = 0; kk < TKC; kk += 8) {
            int cur = (kk >> 3) & 1;
            if (kk + 8 < TKC) LDFRAG2(cur ^ 1, ST, kk + 8);
            #pragma unroll
            for (int mt = 0; mt < 4; mt++)
                #pragma unroll
                for (int nt = 0; nt < 8; nt++)
                    mma8(acc[mt][nt], af[cur][mt], bf[cur][nt]);
        }
    }

    const float* b2e = b2 + (size_t)e * DM;
    #pragma unroll
    for (int mt = 0; mt < 4; mt++)
        #pragma unroll
        for (int rr = 0; rr < 2; rr++) {
            int lm = wm + mt * 16 + g + rr * 8;
            int mg = m0 + lm;
            if (mg >= cnt) continue;
            int   tok = toks[lm];
            float w   = wts[lm];
            float* dst = out + (size_t)tok * DM;
            #pragma unroll
            for (int nt = 0; nt < 8; nt++) {
                int col = n0 + wn + nt * 8 + tig * 2;
                atomicAdd(dst + col,     w * (acc[mt][nt][rr * 2 + 0] + b2e[col]));
                atomicAdd(dst + col + 1, w * (acc[mt][nt][rr * 2 + 1] + b2e[col + 1]));
            }
        }
    #undef ISSUE2
    #undef LDFRAG2
}

// ---------------------------------------------------------------------------
extern "C" void kernel_launch(void* const* d_in, const int* in_sizes, int n_in,
                              void* d_out, int out_size) {
    const float* x    = (const float*)d_in[0];
    const float* Wr   = (const float*)d_in[1];
    const float* temp = (const float*)d_in[2];
    const float* W1   = (const float*)d_in[3];
    const float* b1   = (const float*)d_in[4];
    const float* W2   = (const float*)d_in[5];
    const float* b2   = (const float*)d_in[6];
    float* out = (float*)d_out;

    int T  = in_sizes[0] / DM;
    int MB = (T + 127) / 128;

    const int DSM = NSTG * STGB;   // 98304
    cudaFuncSetAttribute(gemm1_k, cudaFuncAttributeMaxDynamicSharedMemorySize, DSM);
    cudaFuncSetAttribute(gemm2_k, cudaFuncAttributeMaxDynamicSharedMemorySize, DSM);

    cudaMemsetAsync(d_out, 0, (size_t)out_size * sizeof(float), 0);
    init_k<<<1, 32>>>();
    router_k<<<T, 256>>>(x, Wr, temp);

    dim3 g1(FF / 64, MB, NE);
    gemm1_k<<<g1, 128, DSM>>>(x, W1, b1);

    dim3 g2(DM / 128, MB, NE);
    gemm2_k<<<g2, 128, DSM>>>(W2, b2, out);
}